// round 14
// baseline (speedup 1.0000x reference)
#include <cuda_runtime.h>
#include <math.h>
#include <stdint.h>

#define Bq  2
#define Tq  1024
#define Hh  8
#define Dd  128
#define HIDN 1024
#define BT  (Bq*Tq)

#if defined(__CUDA_ARCH_FEAT_SM103_ALL) || defined(__CUDA_ARCH_FEAT_SM100_ALL)
#define HAS_TCGEN05 1
#else
#define HAS_TCGEN05 0
#endif

// ---------------- scratch (device globals; no allocation allowed) ----------------
__device__ float g_pre[3ull*BT*HIDN];      // qpre,kpre,vpre (fp32)
__device__ float g_qkvn[3ull*BT*HIDN];     // qn,kn,vn (fp32)
__device__ float g_nar[2ull*BT*Dd];        // fa, gab (tf32-rounded by epilogue)
__device__ float g_lr[2ull*BT*HIDN];       // eg (exp of g), gateb (fp32)
__device__ float g_betab[BT*Hh];
__device__ float g_qkt[BT*Hh];             // precomputed q_t . k_t
__device__ float g_attn[BT*HIDN];          // tf32-rounded by out_norm_gate
__device__ float g_xtf[(size_t)BT*HIDN];   // tf32(x)
__device__ float g_wtf[4ull*1048576 + 4ull*131072];  // tf32 weights packed

// packed weight offsets (floats)
#define OWQ  0ull
#define OWK  1048576ull
#define OWV  2097152ull
#define OWO  3145728ull
#define OWFA 4194304ull
#define OWGA 4325376ull
#define OWFB 4456448ull
#define OWGB 4587520ull

// ============================ PTX helpers ============================
__device__ __forceinline__ uint32_t smem_u32(const void* p) {
    uint32_t a;
    asm("{ .reg .u64 t; cvta.to.shared.u64 t, %1; cvt.u32.u64 %0, t; }" : "=r"(a) : "l"(p));
    return a;
}
__device__ __forceinline__ float tf32r(float v) {
    uint32_t u;
    asm("cvt.rna.tf32.f32 %0, %1;" : "=r"(u) : "f"(v));
    return __uint_as_float(u);
}
__device__ __forceinline__ void cp16(uint32_t saddr, const void* gaddr) {
    asm volatile("cp.async.cg.shared.global [%0], [%1], 16;" :: "r"(saddr), "l"(gaddr) : "memory");
}
#define CP_COMMIT()  asm volatile("cp.async.commit_group;" ::: "memory")
#define CP_WAIT_1()  asm volatile("cp.async.wait_group 1;" ::: "memory")
#define CP_WAIT_0()  asm volatile("cp.async.wait_group 0;" ::: "memory")

#if HAS_TCGEN05
#define MBARRIER_INIT(addr, cnt) \
    asm volatile("mbarrier.init.shared.b64 [%0], %1;" :: "r"(addr), "r"(cnt) : "memory")

#define MBARRIER_WAIT_PARITY(mbar_smem_addr, phase_parity) do { \
    uint32_t _mbar = (uint32_t)(mbar_smem_addr); \
    uint32_t _parity = (uint32_t)(phase_parity); \
    uint32_t _done; \
    asm volatile( \
        "{\n\t.reg .pred p;\n\t" \
        "mbarrier.try_wait.parity.acquire.cta.shared::cta.b64 p, [%1], %2;\n\t" \
        "selp.b32 %0, 1, 0, p;\n\t}" \
        : "=r"(_done) : "r"(_mbar), "r"(_parity) : "memory"); \
    if (!_done) { \
        asm volatile( \
            "{\n\t.reg .pred P1;\n\t" \
            "WAIT_LOOP_%=:\n\t" \
            "mbarrier.try_wait.parity.acquire.cta.shared::cta.b64 P1, [%0], %1, 0x989680;\n\t" \
            "@P1 bra.uni WAIT_DONE_%=;\n\t" \
            "bra.uni WAIT_LOOP_%=;\n\t" \
            "WAIT_DONE_%=:\n\t}" \
            :: "r"(_mbar), "r"(_parity) : "memory"); \
    } \
} while(0)

#define TCGEN05_ALLOC(smem_result_addr, nCols) \
    asm volatile("tcgen05.alloc.cta_group::1.sync.aligned.shared::cta.b32 [%0], %1;" \
        :: "r"((uint32_t)(smem_result_addr)), "r"((uint32_t)(nCols)) : "memory")
#define TCGEN05_DEALLOC(tmem_addr, nCols) \
    asm volatile("tcgen05.dealloc.cta_group::1.sync.aligned.b32 %0, %1;" \
        :: "r"(tmem_addr), "r"((uint32_t)(nCols)))
#define TCGEN05_RELINQUISH() \
    asm volatile("tcgen05.relinquish_alloc_permit.cta_group::1.sync.aligned;")
#define TCGEN05_COMMIT(mbar_smem_addr) \
    asm volatile("tcgen05.commit.cta_group::1.mbarrier::arrive::one.shared::cluster.b64 [%0];" \
        :: "r"((uint32_t)(mbar_smem_addr)) : "memory")
#define TCGEN05_FENCE_AFTER() \
    asm volatile("tcgen05.fence::after_thread_sync;" ::: "memory")
#define TCGEN05_FENCE_BEFORE() \
    asm volatile("tcgen05.fence::before_thread_sync;" ::: "memory")
#define TCGEN05_WAIT_LD() \
    asm volatile("tcgen05.wait::ld.sync.aligned;" ::: "memory")
#define FENCE_ASYNC_SHARED() \
    asm volatile("fence.proxy.async.shared::cta;" ::: "memory")

#define TCGEN05_MMA_TF32(d_tmem, a_desc, b_desc, idesc, enable_d) do { \
    uint32_t _en = (enable_d) ? 1u : 0u; \
    uint32_t _zero = 0u; \
    asm volatile( \
        "{\n\t.reg .pred p;\n\tsetp.ne.u32 p, %6, 0;\n\t" \
        "tcgen05.mma.cta_group::1.kind::tf32 [%0], %1, %2, %3, {%4, %4, %4, %4}, p;\n\t}" \
        :: "r"(d_tmem), "l"(a_desc), "l"(b_desc), "r"(idesc), \
           "r"(_zero), "r"(_zero), "r"(_en) : "memory"); \
} while(0)

#define TCGEN05_LD_32X32B_X32(r, tmem_addr) \
    asm volatile( \
        "tcgen05.ld.sync.aligned.32x32b.x32.b32 " \
        "{%0, %1, %2, %3, %4, %5, %6, %7, " \
        " %8, %9, %10, %11, %12, %13, %14, %15, " \
        " %16, %17, %18, %19, %20, %21, %22, %23, " \
        " %24, %25, %26, %27, %28, %29, %30, %31}, [%32];" \
        : "=r"((r)[0]),  "=r"((r)[1]),  "=r"((r)[2]),  "=r"((r)[3]), \
          "=r"((r)[4]),  "=r"((r)[5]),  "=r"((r)[6]),  "=r"((r)[7]), \
          "=r"((r)[8]),  "=r"((r)[9]),  "=r"((r)[10]), "=r"((r)[11]), \
          "=r"((r)[12]), "=r"((r)[13]), "=r"((r)[14]), "=r"((r)[15]), \
          "=r"((r)[16]), "=r"((r)[17]), "=r"((r)[18]), "=r"((r)[19]), \
          "=r"((r)[20]), "=r"((r)[21]), "=r"((r)[22]), "=r"((r)[23]), \
          "=r"((r)[24]), "=r"((r)[25]), "=r"((r)[26]), "=r"((r)[27]), \
          "=r"((r)[28]), "=r"((r)[29]), "=r"((r)[30]), "=r"((r)[31]) \
        : "r"(tmem_addr))

static constexpr uint64_t SMEM_DESC_BASE_SW128 =
    (uint64_t(2)  << 61) | (uint64_t(1) << 46) | (uint64_t(64) << 32) | (uint64_t(1) << 16);
#define MAKE_SMEM_DESC(base_addr) \
    (SMEM_DESC_BASE_SW128 | ((uint64_t)((base_addr) >> 4) & 0x3FFF))
#endif  // HAS_TCGEN05

// idesc: dtype=F32(1<<4), atype=TF32(2<<7), btype=TF32(2<<10), N=128(16<<17), M=128(8<<24)
#define IDESC_TF32 0x08200910u

// -------- tf32 conversion pass: x + 8 weights, segment per blockIdx.y --------
__global__ void cvt_tf32_all(const float* __restrict__ x,
                             const float* __restrict__ Wq, const float* __restrict__ Wk,
                             const float* __restrict__ Wv, const float* __restrict__ Wo,
                             const float* __restrict__ Wfa, const float* __restrict__ Wga,
                             const float* __restrict__ Wfb, const float* __restrict__ Wgb) {
    int seg = blockIdx.y;
    const float* src; float* dst; size_t n;
    switch (seg) {
        case 0: src = x;   dst = g_xtf;          n = (size_t)BT * HIDN; break;
        case 1: src = Wq;  dst = g_wtf + OWQ;    n = 1048576; break;
        case 2: src = Wk;  dst = g_wtf + OWK;    n = 1048576; break;
        case 3: src = Wv;  dst = g_wtf + OWV;    n = 1048576; break;
        case 4: src = Wo;  dst = g_wtf + OWO;    n = 1048576; break;
        case 5: src = Wfa; dst = g_wtf + OWFA;   n = 131072; break;
        case 6: src = Wga; dst = g_wtf + OWGA;   n = 131072; break;
        case 7: src = Wfb; dst = g_wtf + OWFB;   n = 131072; break;
        default: src = Wgb; dst = g_wtf + OWGB;  n = 131072; break;
    }
    size_t i = ((size_t)blockIdx.x * blockDim.x + threadIdx.x) * 4;
    if (i >= n) return;
    float4 v = *(const float4*)(src + i);
    v.x = tf32r(v.x); v.y = tf32r(v.y); v.z = tf32r(v.z); v.w = tf32r(v.w);
    *(float4*)(dst + i) = v;
}

// ============ GEMM: C tile = A[M,K] * W[N,K]^T, 128x128 tiles ============
#define CHUNK_BYTES 16384   // 128 rows * 32 fp32 * 4B
__global__ void __launch_bounds__(256, 3)
gemm_tc(const float* __restrict__ A, size_t sAz,
        const float* __restrict__ W0, const float* __restrict__ W1, const float* __restrict__ W2,
        float* __restrict__ C, size_t sCz, int N, int K, int round_out) {
    extern __shared__ char dynraw[];

    const float* W = (blockIdx.z == 0) ? W0 : (blockIdx.z == 1 ? W1 : W2);
    A += sAz * blockIdx.z;
    C += sCz * blockIdx.z;

    int tid = threadIdx.x;
    int bm = blockIdx.y * 128, bn = blockIdx.x * 128;

    uint32_t dynaddr = smem_u32(dynraw);
    uint32_t base = (dynaddr + 1023u) & ~1023u;

#if HAS_TCGEN05
    __shared__ uint32_t tptr_slot;
    __shared__ uint64_t mbar[2];
    uint32_t mb0 = smem_u32(&mbar[0]);
    uint32_t mb1 = smem_u32(&mbar[1]);

    if (tid < 32) {
        TCGEN05_ALLOC(smem_u32(&tptr_slot), 128);
        TCGEN05_RELINQUISH();
    }
    if (tid == 0) { MBARRIER_INIT(mb0, 1); MBARRIER_INIT(mb1, 1); }
    __syncthreads();
    uint32_t tmem = tptr_slot;

    const float* Ag = A + (size_t)bm * K;
    const float* Bg = W + (size_t)bn * K;
    int nk = K >> 5;
    int ph0 = 0, ph1 = 0;

    // prologue: chunk 0 into buf0
    {
        uint32_t a0 = base, b0 = base + CHUNK_BYTES;
#pragma unroll
        for (int u = 0; u < 4; u++) {
            int id = u * 256 + tid;
            int r = id >> 3, s = id & 7;
            uint32_t so = (uint32_t)(r * 128 + ((s ^ (r & 7)) * 16));
            cp16(a0 + so, Ag + (size_t)r * K + s * 4);
            cp16(b0 + so, Bg + (size_t)r * K + s * 4);
        }
        CP_COMMIT();
    }

    for (int kt = 0; kt < nk; kt++) {
        int buf = kt & 1;
        if (kt + 1 < nk) {
            int nbuf = buf ^ 1;
            if (kt >= 1) {
                if (nbuf == 0) { MBARRIER_WAIT_PARITY(mb0, ph0); ph0 ^= 1; }
                else           { MBARRIER_WAIT_PARITY(mb1, ph1); ph1 ^= 1; }
            }
            uint32_t an = base + nbuf * (2 * CHUNK_BYTES), bnn = an + CHUNK_BYTES;
            const float* Ak = Ag + (kt + 1) * 32;
            const float* Bk = Bg + (kt + 1) * 32;
#pragma unroll
            for (int u = 0; u < 4; u++) {
                int id = u * 256 + tid;
                int r = id >> 3, s = id & 7;
                uint32_t so = (uint32_t)(r * 128 + ((s ^ (r & 7)) * 16));
                cp16(an + so, Ak + (size_t)r * K + s * 4);
                cp16(bnn + so, Bk + (size_t)r * K + s * 4);
            }
            CP_COMMIT();
            CP_WAIT_1();
        } else {
            CP_WAIT_0();
        }
        FENCE_ASYNC_SHARED();
        __syncthreads();
        if (tid == 0) {
            uint32_t aaddr = base + buf * (2 * CHUNK_BYTES);
            uint64_t ad = MAKE_SMEM_DESC(aaddr);
            uint64_t bd = MAKE_SMEM_DESC(aaddr + CHUNK_BYTES);
#pragma unroll
            for (int s = 0; s < 4; s++)
                TCGEN05_MMA_TF32(tmem, ad + s * 2, bd + s * 2, IDESC_TF32, (kt > 0) || (s > 0));
            TCGEN05_COMMIT((buf == 0) ? mb0 : mb1);
        }
    }
    if (((nk - 1) & 1) == 0) { MBARRIER_WAIT_PARITY(mb0, ph0); }
    else                     { MBARRIER_WAIT_PARITY(mb1, ph1); }
    TCGEN05_FENCE_AFTER();

    // 8-warp epilogue: warps 0-3 cols 0-63, warps 4-7 cols 64-127
    int wid = tid >> 5, lane = tid & 31;
    int m = bm + (wid & 3) * 32 + lane;
    int nbbase = (wid >> 2) * 2;
#pragma unroll
    for (int it = 0; it < 2; it++) {
        int nb = nbbase + it;
        uint32_t r[32];
        TCGEN05_LD_32X32B_X32(r, tmem + nb * 32);
        TCGEN05_WAIT_LD();
        float4* dst = (float4*)&C[(size_t)m * N + bn + nb * 32];
#pragma unroll
        for (int c = 0; c < 8; c++) {
            float4 v = make_float4(__uint_as_float(r[4*c]), __uint_as_float(r[4*c+1]),
                                   __uint_as_float(r[4*c+2]), __uint_as_float(r[4*c+3]));
            if (round_out) { v.x = tf32r(v.x); v.y = tf32r(v.y); v.z = tf32r(v.z); v.w = tf32r(v.w); }
            dst[c] = v;
        }
    }
    TCGEN05_FENCE_BEFORE();
    __syncthreads();
    if (tid < 32) TCGEN05_DEALLOC(tmem, 128);
#else
    // ---------------- SIMT fallback (plain sm_103 target; not expected to run) ----------------
    char* buf_ptr = dynraw + (base - dynaddr);
    float* As = (float*)buf_ptr;
    float* Bs = As + 8 * 128;
    int tx = tid & 15, ty = tid >> 4;
    float acc[8][8];
#pragma unroll
    for (int i = 0; i < 8; i++)
#pragma unroll
        for (int j = 0; j < 8; j++) acc[i][j] = 0.f;

    int nk8 = K >> 3;
    for (int kt = 0; kt < nk8; kt++) {
        __syncthreads();
        {
            int r = tid >> 1, cg = (tid & 1) * 4;
            float4 va = *(const float4*)(A + (size_t)(bm + r) * K + kt * 8 + cg);
            float4 vb = *(const float4*)(W + (size_t)(bn + r) * K + kt * 8 + cg);
            As[(cg + 0) * 128 + r] = va.x; As[(cg + 1) * 128 + r] = va.y;
            As[(cg + 2) * 128 + r] = va.z; As[(cg + 3) * 128 + r] = va.w;
            Bs[(cg + 0) * 128 + r] = vb.x; Bs[(cg + 1) * 128 + r] = vb.y;
            Bs[(cg + 2) * 128 + r] = vb.z; Bs[(cg + 3) * 128 + r] = vb.w;
        }
        __syncthreads();
#pragma unroll
        for (int kk = 0; kk < 8; kk++) {
            float av[8], bv[8];
#pragma unroll
            for (int i = 0; i < 8; i++) av[i] = As[kk * 128 + ty * 8 + i];
#pragma unroll
            for (int j = 0; j < 8; j++) bv[j] = Bs[kk * 128 + tx * 8 + j];
#pragma unroll
            for (int i = 0; i < 8; i++)
#pragma unroll
                for (int j = 0; j < 8; j++)
                    acc[i][j] = fmaf(av[i], bv[j], acc[i][j]);
        }
    }
#pragma unroll
    for (int i = 0; i < 8; i++) {
        int m = bm + ty * 8 + i;
#pragma unroll
        for (int j = 0; j < 8; j++) {
            float v = acc[i][j];
            if (round_out) v = tf32r(v);
            C[(size_t)m * N + bn + tx * 8 + j] = v;
        }
    }
#endif
}

// ---- beta = sigmoid(x @ Wb^T): one warp per (row, head) ----
__global__ void beta_kernel(const float* __restrict__ x, const float* __restrict__ Wb,
                            float* __restrict__ out) {
    int row = blockIdx.x;
    int h = threadIdx.x >> 5;
    int l = threadIdx.x & 31;
    const float* xr = x + (size_t)row * HIDN;
    const float* wr = Wb + (size_t)h * HIDN;
    float acc = 0.f;
#pragma unroll 8
    for (int i = l; i < HIDN; i += 32) acc = fmaf(xr[i], wr[i], acc);
#pragma unroll
    for (int off = 16; off > 0; off >>= 1) acc += __shfl_xor_sync(0xffffffffu, acc, off);
    if (l == 0) out[row * Hh + h] = 1.f / (1.f + expf(-acc));
}

// ---- qkt[bt][h] = dot(q_row, k_row): one warp per (row, head) ----
__global__ void qk_kernel(const float* __restrict__ q, const float* __restrict__ k,
                          float* __restrict__ out) {
    int row = blockIdx.x;
    int h = threadIdx.x >> 5;
    int l = threadIdx.x & 31;
    size_t base = (size_t)row * HIDN + h * Dd + l * 4;
    float4 a = *(const float4*)(q + base);
    float4 b = *(const float4*)(k + base);
    float acc = a.x * b.x;
    acc = fmaf(a.y, b.y, acc);
    acc = fmaf(a.z, b.z, acc);
    acc = fmaf(a.w, b.w, acc);
#pragma unroll
    for (int off = 16; off > 0; off >>= 1) acc += __shfl_xor_sync(0xffffffffu, acc, off);
    if (l == 0) out[row * Hh + h] = acc;
}

// -------- depthwise causal conv (K=4) + SiLU + optional per-head RMSNorm --------
__global__ void conv_silu_norm(const float* __restrict__ pre_base, const float* __restrict__ wq,
                               const float* __restrict__ wk, const float* __restrict__ wv,
                               float* __restrict__ out_base) {
    int which = blockIdx.y;
    const float* w = (which == 0) ? wq : (which == 1 ? wk : wv);
    const float* pre = pre_base + (size_t)which * BT * HIDN;
    float* out = out_base + (size_t)which * BT * HIDN;
    float postscale = (which == 0) ? (1.f / 128.f) : (which == 1 ? 0.08838834764831845f : 1.f);
    int do_norm = (which < 2);

    int blk = blockIdx.x;
    int h = blk % Hh;
    int bt = blk / Hh;
    int t = bt % Tq;
    int d = threadIdx.x;
    int c = h * Dd + d;

    float acc = 0.f;
#pragma unroll
    for (int j = 0; j < 4; j++) {
        int tt = t - 3 + j;
        if (tt >= 0) acc += pre[(size_t)(bt - t + tt) * HIDN + c] * w[c * 4 + j];
    }
    acc = acc / (1.f + expf(-acc));
    float val = acc;
    if (do_norm) {
        float ss = acc * acc;
#pragma unroll
        for (int off = 16; off > 0; off >>= 1) ss += __shfl_xor_sync(0xffffffffu, ss, off);
        __shared__ float sh[4];
        if ((threadIdx.x & 31) == 0) sh[threadIdx.x >> 5] = ss;
        __syncthreads();
        float tot = sh[0] + sh[1] + sh[2] + sh[3];
        val = acc * rsqrtf(tot * (1.f / 128.f) + 1e-6f) * postscale;
    }
    out[(size_t)bt * HIDN + c] = val;
}

// -------- eg = exp(-exp(A_log[h]) * softplus(a + dt_bias)) --------
__global__ void g_transform(float* __restrict__ a, const float* __restrict__ dt_bias,
                            const float* __restrict__ A_log) {
    int idx = blockIdx.x * blockDim.x + threadIdx.x;
    if (idx >= BT * HIDN) return;
    int c = idx % HIDN;
    int h = c / Dd;
    float x = a[idx] + dt_bias[c];
    float sp = (x > 0.f) ? (x + log1pf(expf(-x))) : log1pf(expf(x));
    a[idx] = expf(-expf(A_log[h]) * sp);
}

// ------- gated delta-rule scan: 32 lanes/col, depth-2 prefetch, qk hoisted -------
// grid (16 bh, 32 colgroups of 4), 128 threads (4 warps = 4 cols).
__global__ void __launch_bounds__(128, 4)
scan_kernel(const float* __restrict__ q, const float* __restrict__ k,
            const float* __restrict__ v, const float* __restrict__ eg,
            const float* __restrict__ beta, const float* __restrict__ qkt,
            float* __restrict__ out) {
    int bh = blockIdx.x;
    int b = bh >> 3, h = bh & 7;
    int warp = threadIdx.x >> 5, lane = threadIdx.x & 31;
    int col = blockIdx.y * 4 + warp;
    int rbase = lane * 4;
    size_t rowbase = (size_t)b * Tq * HIDN + h * Dd;
    int sbase = b * Tq * Hh + h;

    float4 S = make_float4(0.f, 0.f, 0.f, 0.f);

    // pipeline registers: current (c), next (n)
    float4 kc, qc, ec, kn, qn, en;
    float vc, bc, qkc, vn_, bn_, qkn;
    kc = *(const float4*)(k  + rowbase + rbase);
    qc = *(const float4*)(q  + rowbase + rbase);
    ec = *(const float4*)(eg + rowbase + rbase);
    vc = v[rowbase + col];
    bc = beta[sbase];
    qkc = qkt[sbase];
    {
        size_t r1 = rowbase + HIDN;
        kn = *(const float4*)(k  + r1 + rbase);
        qn = *(const float4*)(q  + r1 + rbase);
        en = *(const float4*)(eg + r1 + rbase);
        vn_ = v[r1 + col];
        bn_ = beta[sbase + Hh];
        qkn = qkt[sbase + Hh];
    }

    for (int t = 0; t < Tq; t++) {
        size_t row = rowbase + (size_t)t * HIDN;
        // issue loads for t+2 (clamped)
        int t2 = (t + 2 < Tq) ? (t + 2) : (Tq - 1);
        size_t row2 = rowbase + (size_t)t2 * HIDN;
        float4 k2 = *(const float4*)(k  + row2 + rbase);
        float4 q2 = *(const float4*)(q  + row2 + rbase);
        float4 e2 = *(const float4*)(eg + row2 + rbase);
        float v2 = v[row2 + col];
        float b2 = beta[sbase + t2 * Hh];
        float qk2 = qkt[sbase + t2 * Hh];

        // phase 1: decay + kv/qs partials
        float s0 = S.x * ec.x, s1 = S.y * ec.y, s2 = S.z * ec.z, s3 = S.w * ec.w;
        float kv = kc.x * s0; kv = fmaf(kc.y, s1, kv); kv = fmaf(kc.z, s2, kv); kv = fmaf(kc.w, s3, kv);
        float qs = qc.x * s0; qs = fmaf(qc.y, s1, qs); qs = fmaf(qc.z, s2, qs); qs = fmaf(qc.w, s3, qs);

        // critical reduction: kv alone (delta depends only on this)
#pragma unroll
        for (int off = 1; off < 32; off <<= 1)
            kv += __shfl_xor_sync(0xffffffffu, kv, off);
        float delta = bc * (vc - kv);

        // state update (recurrence critical path ends here)
        S.x = fmaf(kc.x, delta, s0);
        S.y = fmaf(kc.y, delta, s1);
        S.z = fmaf(kc.z, delta, s2);
        S.w = fmaf(kc.w, delta, s3);

        // off-path: qs reduction + output
#pragma unroll
        for (int off = 1; off < 32; off <<= 1)
            qs += __shfl_xor_sync(0xffffffffu, qs, off);
        if (lane == 0) out[row + col] = fmaf(qkc, delta, qs);

        // rotate pipeline
        kc = kn; qc = qn; ec = en; vc = vn_; bc = bn_; qkc = qkn;
        kn = k2; qn = q2; en = e2; vn_ = v2; bn_ = b2; qkn = qk2;
    }
}

// -------- output RMSNorm * o_norm_w * sigmoid(gate); writes tf32-rounded --------
__global__ void out_norm_gate(float* __restrict__ attn, const float* __restrict__ gate,
                              const float* __restrict__ onw) {
    int blk = blockIdx.x;
    int h = blk % Hh;
    int bt = blk / Hh;
    int d = threadIdx.x;
    size_t idx = (size_t)bt * HIDN + h * Dd + d;
    float val = attn[idx];
    float ss = val * val;
#pragma unroll
    for (int off = 16; off > 0; off >>= 1) ss += __shfl_xor_sync(0xffffffffu, ss, off);
    __shared__ float sh[4];
    if ((threadIdx.x & 31) == 0) sh[threadIdx.x >> 5] = ss;
    __syncthreads();
    float tot = sh[0] + sh[1] + sh[2] + sh[3];
    float gt = gate[idx];
    attn[idx] = tf32r(val * rsqrtf(tot * (1.f / 128.f) + 1e-5f) * onw[d]
              * (1.f / (1.f + expf(-gt))));
}

// ---------------------------------- launch ----------------------------------
extern "C" void kernel_launch(void* const* d_in, const int* in_sizes, int n_in,
                              void* d_out, int out_size) {
    const float* x       = (const float*)d_in[0];
    const float* Wq      = (const float*)d_in[1];
    const float* Wk      = (const float*)d_in[2];
    const float* Wv      = (const float*)d_in[3];
    const float* wq_conv = (const float*)d_in[4];
    const float* wk_conv = (const float*)d_in[5];
    const float* wv_conv = (const float*)d_in[6];
    const float* Wfa     = (const float*)d_in[7];
    const float* Wfb     = (const float*)d_in[8];
    const float* Wb      = (const float*)d_in[9];
    const float* Wga     = (const float*)d_in[10];
    const float* Wgb     = (const float*)d_in[11];
    const float* A_log   = (const float*)d_in[12];
    const float* dt_bias = (const float*)d_in[13];
    const float* onw     = (const float*)d_in[14];
    const float* Wo      = (const float*)d_in[15];
    float* out = (float*)d_out;

    float *pre, *qkvn, *nar, *lr, *betab, *qkt, *attn, *xtf, *wtf;
    cudaGetSymbolAddress((void**)&pre, g_pre);
    cudaGetSymbolAddress((void**)&qkvn, g_qkvn);
    cudaGetSymbolAddress((void**)&nar, g_nar);
    cudaGetSymbolAddress((void**)&lr, g_lr);
    cudaGetSymbolAddress((void**)&betab, g_betab);
    cudaGetSymbolAddress((void**)&qkt, g_qkt);
    cudaGetSymbolAddress((void**)&attn, g_attn);
    cudaGetSymbolAddress((void**)&xtf, g_xtf);
    cudaGetSymbolAddress((void**)&wtf, g_wtf);

    const size_t S1 = (size_t)BT * HIDN;
    const size_t SD = (size_t)BT * Dd;
    const int SMEM_GEMM = 4 * CHUNK_BYTES + 1024;   // 66560
    cudaFuncSetAttribute(gemm_tc, cudaFuncAttributeMaxDynamicSharedMemorySize, SMEM_GEMM);

    // side streams + events, created ONCE on the first (uncaptured) call
    static cudaStream_t s1 = nullptr, s2 = nullptr;
    static cudaEvent_t evFork = nullptr, ev1 = nullptr, ev2 = nullptr;
    if (!s1) {
        cudaStreamCreateWithFlags(&s1, cudaStreamNonBlocking);
        cudaStreamCreateWithFlags(&s2, cudaStreamNonBlocking);
        cudaEventCreateWithFlags(&evFork, cudaEventDisableTiming);
        cudaEventCreateWithFlags(&ev1, cudaEventDisableTiming);
        cudaEventCreateWithFlags(&ev2, cudaEventDisableTiming);
    }

    // fork: beta depends only on raw x
    cudaEventRecord(evFork, 0);
    cudaStreamWaitEvent(s2, evFork, 0);
    beta_kernel<<<BT, 256, 0, s2>>>(x, Wb, betab);
    cudaEventRecord(ev2, s2);

    // tf32 pre-conversion on main stream
    cvt_tf32_all<<<dim3(2048, 9), 256>>>(x, Wq, Wk, Wv, Wo, Wfa, Wga, Wfb, Wgb);
    cudaEventRecord(evFork, 0);
    cudaStreamWaitEvent(s1, evFork, 0);

    // side branch on s1: nar -> lr -> g_transform
    gemm_tc<<<dim3(1, 16, 2), 256, SMEM_GEMM, s1>>>(xtf, 0, wtf + OWFA, wtf + OWGA, wtf + OWGA,
                                                    nar, SD, Dd, HIDN, 1);
    gemm_tc<<<dim3(8, 16, 2), 256, SMEM_GEMM, s1>>>(nar, SD, wtf + OWFB, wtf + OWGB, wtf + OWGB,
                                                    lr, S1, HIDN, Dd, 0);
    g_transform<<<(BT * HIDN + 255) / 256, 256, 0, s1>>>(lr, dt_bias, A_log);
    cudaEventRecord(ev1, s1);

    // main branch: QKV projections -> conv/silu/norm -> qk precompute
    gemm_tc<<<dim3(8, 16, 3), 256, SMEM_GEMM>>>(xtf, 0, wtf + OWQ, wtf + OWK, wtf + OWV,
                                                pre, S1, HIDN, HIDN, 0);
    conv_silu_norm<<<dim3(BT * Hh, 3), 128>>>(pre, wq_conv, wk_conv, wv_conv, qkvn);
    qk_kernel<<<BT, 256>>>(qkvn, qkvn + S1, qkt);

    // join: scan needs qkvn+qkt (main), lr (s1), betab (s2)
    cudaStreamWaitEvent(0, ev1, 0);
    cudaStreamWaitEvent(0, ev2, 0);

    // recurrence (register-only warp-synchronous scan, depth-2 prefetch)
    scan_kernel<<<dim3(16, 32), 128>>>(qkvn, qkvn + S1, qkvn + 2 * S1, lr, betab, qkt, attn);

    // output norm/gate (writes tf32-rounded attn) + final projection
    out_norm_gate<<<BT * Hh, 128>>>(attn, lr + S1, onw);
    gemm_tc<<<dim3(8, 16, 1), 256, SMEM_GEMM>>>(attn, 0, wtf + OWO, wtf + OWO, wtf + OWO,
                                                out, 0, HIDN, HIDN, 0);
}

// round 15
// speedup vs baseline: 1.1828x; 1.1828x over previous
#include <cuda_runtime.h>
#include <math.h>
#include <stdint.h>

#define Bq  2
#define Tq  1024
#define Hh  8
#define Dd  128
#define HIDN 1024
#define BT  (Bq*Tq)

#if defined(__CUDA_ARCH_FEAT_SM103_ALL) || defined(__CUDA_ARCH_FEAT_SM100_ALL)
#define HAS_TCGEN05 1
#else
#define HAS_TCGEN05 0
#endif

// ---------------- scratch (device globals; no allocation allowed) ----------------
__device__ float g_pre[3ull*BT*HIDN];      // qpre,kpre,vpre (fp32)
__device__ float g_qkvn[3ull*BT*HIDN];     // qn,kn,vn (fp32)
__device__ float g_nar[2ull*BT*Dd];        // fa, gab (tf32-rounded by epilogue)
__device__ float g_lr[2ull*BT*HIDN];       // eg (exp of g), gateb (fp32)
__device__ float g_betab[BT*Hh];
__device__ float g_qkt[BT*Hh];             // precomputed q_t . k_t
__device__ float g_attn[BT*HIDN];          // tf32-rounded by out_norm_gate
__device__ float g_xtf[(size_t)BT*HIDN];   // tf32(x)
__device__ float g_wtf[4ull*1048576 + 4ull*131072];  // tf32 weights packed

// packed weight offsets (floats)
#define OWQ  0ull
#define OWK  1048576ull
#define OWV  2097152ull
#define OWO  3145728ull
#define OWFA 4194304ull
#define OWGA 4325376ull
#define OWFB 4456448ull
#define OWGB 4587520ull

// ============================ PTX helpers ============================
__device__ __forceinline__ uint32_t smem_u32(const void* p) {
    uint32_t a;
    asm("{ .reg .u64 t; cvta.to.shared.u64 t, %1; cvt.u32.u64 %0, t; }" : "=r"(a) : "l"(p));
    return a;
}
__device__ __forceinline__ float tf32r(float v) {
    uint32_t u;
    asm("cvt.rna.tf32.f32 %0, %1;" : "=r"(u) : "f"(v));
    return __uint_as_float(u);
}
__device__ __forceinline__ void cp16(uint32_t saddr, const void* gaddr) {
    asm volatile("cp.async.cg.shared.global [%0], [%1], 16;" :: "r"(saddr), "l"(gaddr) : "memory");
}
#define CP_COMMIT()  asm volatile("cp.async.commit_group;" ::: "memory")
#define CP_WAIT_1()  asm volatile("cp.async.wait_group 1;" ::: "memory")
#define CP_WAIT_0()  asm volatile("cp.async.wait_group 0;" ::: "memory")

#if HAS_TCGEN05
#define MBARRIER_INIT(addr, cnt) \
    asm volatile("mbarrier.init.shared.b64 [%0], %1;" :: "r"(addr), "r"(cnt) : "memory")

#define MBARRIER_WAIT_PARITY(mbar_smem_addr, phase_parity) do { \
    uint32_t _mbar = (uint32_t)(mbar_smem_addr); \
    uint32_t _parity = (uint32_t)(phase_parity); \
    uint32_t _done; \
    asm volatile( \
        "{\n\t.reg .pred p;\n\t" \
        "mbarrier.try_wait.parity.acquire.cta.shared::cta.b64 p, [%1], %2;\n\t" \
        "selp.b32 %0, 1, 0, p;\n\t}" \
        : "=r"(_done) : "r"(_mbar), "r"(_parity) : "memory"); \
    if (!_done) { \
        asm volatile( \
            "{\n\t.reg .pred P1;\n\t" \
            "WAIT_LOOP_%=:\n\t" \
            "mbarrier.try_wait.parity.acquire.cta.shared::cta.b64 P1, [%0], %1, 0x989680;\n\t" \
            "@P1 bra.uni WAIT_DONE_%=;\n\t" \
            "bra.uni WAIT_LOOP_%=;\n\t" \
            "WAIT_DONE_%=:\n\t}" \
            :: "r"(_mbar), "r"(_parity) : "memory"); \
    } \
} while(0)

#define TCGEN05_ALLOC(smem_result_addr, nCols) \
    asm volatile("tcgen05.alloc.cta_group::1.sync.aligned.shared::cta.b32 [%0], %1;" \
        :: "r"((uint32_t)(smem_result_addr)), "r"((uint32_t)(nCols)) : "memory")
#define TCGEN05_DEALLOC(tmem_addr, nCols) \
    asm volatile("tcgen05.dealloc.cta_group::1.sync.aligned.b32 %0, %1;" \
        :: "r"(tmem_addr), "r"((uint32_t)(nCols)))
#define TCGEN05_RELINQUISH() \
    asm volatile("tcgen05.relinquish_alloc_permit.cta_group::1.sync.aligned;")
#define TCGEN05_COMMIT(mbar_smem_addr) \
    asm volatile("tcgen05.commit.cta_group::1.mbarrier::arrive::one.shared::cluster.b64 [%0];" \
        :: "r"((uint32_t)(mbar_smem_addr)) : "memory")
#define TCGEN05_FENCE_AFTER() \
    asm volatile("tcgen05.fence::after_thread_sync;" ::: "memory")
#define TCGEN05_FENCE_BEFORE() \
    asm volatile("tcgen05.fence::before_thread_sync;" ::: "memory")
#define TCGEN05_WAIT_LD() \
    asm volatile("tcgen05.wait::ld.sync.aligned;" ::: "memory")
#define FENCE_ASYNC_SHARED() \
    asm volatile("fence.proxy.async.shared::cta;" ::: "memory")

#define TCGEN05_MMA_TF32(d_tmem, a_desc, b_desc, idesc, enable_d) do { \
    uint32_t _en = (enable_d) ? 1u : 0u; \
    uint32_t _zero = 0u; \
    asm volatile( \
        "{\n\t.reg .pred p;\n\tsetp.ne.u32 p, %6, 0;\n\t" \
        "tcgen05.mma.cta_group::1.kind::tf32 [%0], %1, %2, %3, {%4, %4, %4, %4}, p;\n\t}" \
        :: "r"(d_tmem), "l"(a_desc), "l"(b_desc), "r"(idesc), \
           "r"(_zero), "r"(_zero), "r"(_en) : "memory"); \
} while(0)

#define TCGEN05_LD_32X32B_X32(r, tmem_addr) \
    asm volatile( \
        "tcgen05.ld.sync.aligned.32x32b.x32.b32 " \
        "{%0, %1, %2, %3, %4, %5, %6, %7, " \
        " %8, %9, %10, %11, %12, %13, %14, %15, " \
        " %16, %17, %18, %19, %20, %21, %22, %23, " \
        " %24, %25, %26, %27, %28, %29, %30, %31}, [%32];" \
        : "=r"((r)[0]),  "=r"((r)[1]),  "=r"((r)[2]),  "=r"((r)[3]), \
          "=r"((r)[4]),  "=r"((r)[5]),  "=r"((r)[6]),  "=r"((r)[7]), \
          "=r"((r)[8]),  "=r"((r)[9]),  "=r"((r)[10]), "=r"((r)[11]), \
          "=r"((r)[12]), "=r"((r)[13]), "=r"((r)[14]), "=r"((r)[15]), \
          "=r"((r)[16]), "=r"((r)[17]), "=r"((r)[18]), "=r"((r)[19]), \
          "=r"((r)[20]), "=r"((r)[21]), "=r"((r)[22]), "=r"((r)[23]), \
          "=r"((r)[24]), "=r"((r)[25]), "=r"((r)[26]), "=r"((r)[27]), \
          "=r"((r)[28]), "=r"((r)[29]), "=r"((r)[30]), "=r"((r)[31]) \
        : "r"(tmem_addr))

static constexpr uint64_t SMEM_DESC_BASE_SW128 =
    (uint64_t(2)  << 61) | (uint64_t(1) << 46) | (uint64_t(64) << 32) | (uint64_t(1) << 16);
#define MAKE_SMEM_DESC(base_addr) \
    (SMEM_DESC_BASE_SW128 | ((uint64_t)((base_addr) >> 4) & 0x3FFF))
#endif  // HAS_TCGEN05

// idesc: dtype=F32(1<<4), atype=TF32(2<<7), btype=TF32(2<<10), N=128(16<<17), M=128(8<<24)
#define IDESC_TF32 0x08200910u

// -------- tf32 conversion pass: x + 8 weights, segment per blockIdx.y --------
__global__ void cvt_tf32_all(const float* __restrict__ x,
                             const float* __restrict__ Wq, const float* __restrict__ Wk,
                             const float* __restrict__ Wv, const float* __restrict__ Wo,
                             const float* __restrict__ Wfa, const float* __restrict__ Wga,
                             const float* __restrict__ Wfb, const float* __restrict__ Wgb) {
    int seg = blockIdx.y;
    const float* src; float* dst; size_t n;
    switch (seg) {
        case 0: src = x;   dst = g_xtf;          n = (size_t)BT * HIDN; break;
        case 1: src = Wq;  dst = g_wtf + OWQ;    n = 1048576; break;
        case 2: src = Wk;  dst = g_wtf + OWK;    n = 1048576; break;
        case 3: src = Wv;  dst = g_wtf + OWV;    n = 1048576; break;
        case 4: src = Wo;  dst = g_wtf + OWO;    n = 1048576; break;
        case 5: src = Wfa; dst = g_wtf + OWFA;   n = 131072; break;
        case 6: src = Wga; dst = g_wtf + OWGA;   n = 131072; break;
        case 7: src = Wfb; dst = g_wtf + OWFB;   n = 131072; break;
        default: src = Wgb; dst = g_wtf + OWGB;  n = 131072; break;
    }
    size_t i = ((size_t)blockIdx.x * blockDim.x + threadIdx.x) * 4;
    if (i >= n) return;
    float4 v = *(const float4*)(src + i);
    v.x = tf32r(v.x); v.y = tf32r(v.y); v.z = tf32r(v.z); v.w = tf32r(v.w);
    *(float4*)(dst + i) = v;
}

// ============ GEMM: C tile = A[M,K] * W[N,K]^T, 128x128 tiles ============
#define CHUNK_BYTES 16384   // 128 rows * 32 fp32 * 4B
__global__ void __launch_bounds__(256, 3)
gemm_tc(const float* __restrict__ A, size_t sAz,
        const float* __restrict__ W0, const float* __restrict__ W1, const float* __restrict__ W2,
        float* __restrict__ C, size_t sCz, int N, int K, int round_out) {
    extern __shared__ char dynraw[];

    const float* W = (blockIdx.z == 0) ? W0 : (blockIdx.z == 1 ? W1 : W2);
    A += sAz * blockIdx.z;
    C += sCz * blockIdx.z;

    int tid = threadIdx.x;
    int bm = blockIdx.y * 128, bn = blockIdx.x * 128;

    uint32_t dynaddr = smem_u32(dynraw);
    uint32_t base = (dynaddr + 1023u) & ~1023u;

#if HAS_TCGEN05
    __shared__ uint32_t tptr_slot;
    __shared__ uint64_t mbar[2];
    uint32_t mb0 = smem_u32(&mbar[0]);
    uint32_t mb1 = smem_u32(&mbar[1]);

    if (tid < 32) {
        TCGEN05_ALLOC(smem_u32(&tptr_slot), 128);
        TCGEN05_RELINQUISH();
    }
    if (tid == 0) { MBARRIER_INIT(mb0, 1); MBARRIER_INIT(mb1, 1); }
    __syncthreads();
    uint32_t tmem = tptr_slot;

    const float* Ag = A + (size_t)bm * K;
    const float* Bg = W + (size_t)bn * K;
    int nk = K >> 5;
    int ph0 = 0, ph1 = 0;

    // prologue: chunk 0 into buf0
    {
        uint32_t a0 = base, b0 = base + CHUNK_BYTES;
#pragma unroll
        for (int u = 0; u < 4; u++) {
            int id = u * 256 + tid;
            int r = id >> 3, s = id & 7;
            uint32_t so = (uint32_t)(r * 128 + ((s ^ (r & 7)) * 16));
            cp16(a0 + so, Ag + (size_t)r * K + s * 4);
            cp16(b0 + so, Bg + (size_t)r * K + s * 4);
        }
        CP_COMMIT();
    }

    for (int kt = 0; kt < nk; kt++) {
        int buf = kt & 1;
        if (kt + 1 < nk) {
            int nbuf = buf ^ 1;
            if (kt >= 1) {
                if (nbuf == 0) { MBARRIER_WAIT_PARITY(mb0, ph0); ph0 ^= 1; }
                else           { MBARRIER_WAIT_PARITY(mb1, ph1); ph1 ^= 1; }
            }
            uint32_t an = base + nbuf * (2 * CHUNK_BYTES), bnn = an + CHUNK_BYTES;
            const float* Ak = Ag + (kt + 1) * 32;
            const float* Bk = Bg + (kt + 1) * 32;
#pragma unroll
            for (int u = 0; u < 4; u++) {
                int id = u * 256 + tid;
                int r = id >> 3, s = id & 7;
                uint32_t so = (uint32_t)(r * 128 + ((s ^ (r & 7)) * 16));
                cp16(an + so, Ak + (size_t)r * K + s * 4);
                cp16(bnn + so, Bk + (size_t)r * K + s * 4);
            }
            CP_COMMIT();
            CP_WAIT_1();
        } else {
            CP_WAIT_0();
        }
        FENCE_ASYNC_SHARED();
        __syncthreads();
        if (tid == 0) {
            uint32_t aaddr = base + buf * (2 * CHUNK_BYTES);
            uint64_t ad = MAKE_SMEM_DESC(aaddr);
            uint64_t bd = MAKE_SMEM_DESC(aaddr + CHUNK_BYTES);
#pragma unroll
            for (int s = 0; s < 4; s++)
                TCGEN05_MMA_TF32(tmem, ad + s * 2, bd + s * 2, IDESC_TF32, (kt > 0) || (s > 0));
            TCGEN05_COMMIT((buf == 0) ? mb0 : mb1);
        }
    }
    if (((nk - 1) & 1) == 0) { MBARRIER_WAIT_PARITY(mb0, ph0); }
    else                     { MBARRIER_WAIT_PARITY(mb1, ph1); }
    TCGEN05_FENCE_AFTER();

    // 8-warp epilogue: warps 0-3 cols 0-63, warps 4-7 cols 64-127
    int wid = tid >> 5, lane = tid & 31;
    int m = bm + (wid & 3) * 32 + lane;
    int nbbase = (wid >> 2) * 2;
#pragma unroll
    for (int it = 0; it < 2; it++) {
        int nb = nbbase + it;
        uint32_t r[32];
        TCGEN05_LD_32X32B_X32(r, tmem + nb * 32);
        TCGEN05_WAIT_LD();
        float4* dst = (float4*)&C[(size_t)m * N + bn + nb * 32];
#pragma unroll
        for (int c = 0; c < 8; c++) {
            float4 v = make_float4(__uint_as_float(r[4*c]), __uint_as_float(r[4*c+1]),
                                   __uint_as_float(r[4*c+2]), __uint_as_float(r[4*c+3]));
            if (round_out) { v.x = tf32r(v.x); v.y = tf32r(v.y); v.z = tf32r(v.z); v.w = tf32r(v.w); }
            dst[c] = v;
        }
    }
    TCGEN05_FENCE_BEFORE();
    __syncthreads();
    if (tid < 32) TCGEN05_DEALLOC(tmem, 128);
#else
    // ---------------- SIMT fallback (plain sm_103 target; not expected to run) ----------------
    char* buf_ptr = dynraw + (base - dynaddr);
    float* As = (float*)buf_ptr;
    float* Bs = As + 8 * 128;
    int tx = tid & 15, ty = tid >> 4;
    float acc[8][8];
#pragma unroll
    for (int i = 0; i < 8; i++)
#pragma unroll
        for (int j = 0; j < 8; j++) acc[i][j] = 0.f;

    int nk8 = K >> 3;
    for (int kt = 0; kt < nk8; kt++) {
        __syncthreads();
        {
            int r = tid >> 1, cg = (tid & 1) * 4;
            float4 va = *(const float4*)(A + (size_t)(bm + r) * K + kt * 8 + cg);
            float4 vb = *(const float4*)(W + (size_t)(bn + r) * K + kt * 8 + cg);
            As[(cg + 0) * 128 + r] = va.x; As[(cg + 1) * 128 + r] = va.y;
            As[(cg + 2) * 128 + r] = va.z; As[(cg + 3) * 128 + r] = va.w;
            Bs[(cg + 0) * 128 + r] = vb.x; Bs[(cg + 1) * 128 + r] = vb.y;
            Bs[(cg + 2) * 128 + r] = vb.z; Bs[(cg + 3) * 128 + r] = vb.w;
        }
        __syncthreads();
#pragma unroll
        for (int kk = 0; kk < 8; kk++) {
            float av[8], bv[8];
#pragma unroll
            for (int i = 0; i < 8; i++) av[i] = As[kk * 128 + ty * 8 + i];
#pragma unroll
            for (int j = 0; j < 8; j++) bv[j] = Bs[kk * 128 + tx * 8 + j];
#pragma unroll
            for (int i = 0; i < 8; i++)
#pragma unroll
                for (int j = 0; j < 8; j++)
                    acc[i][j] = fmaf(av[i], bv[j], acc[i][j]);
        }
    }
#pragma unroll
    for (int i = 0; i < 8; i++) {
        int m = bm + ty * 8 + i;
#pragma unroll
        for (int j = 0; j < 8; j++) {
            float v = acc[i][j];
            if (round_out) v = tf32r(v);
            C[(size_t)m * N + bn + tx * 8 + j] = v;
        }
    }
#endif
}

// ---- beta = sigmoid(x @ Wb^T): one warp per (row, head) ----
__global__ void beta_kernel(const float* __restrict__ x, const float* __restrict__ Wb,
                            float* __restrict__ out) {
    int row = blockIdx.x;
    int h = threadIdx.x >> 5;
    int l = threadIdx.x & 31;
    const float* xr = x + (size_t)row * HIDN;
    const float* wr = Wb + (size_t)h * HIDN;
    float acc = 0.f;
#pragma unroll 8
    for (int i = l; i < HIDN; i += 32) acc = fmaf(xr[i], wr[i], acc);
#pragma unroll
    for (int off = 16; off > 0; off >>= 1) acc += __shfl_xor_sync(0xffffffffu, acc, off);
    if (l == 0) out[row * Hh + h] = 1.f / (1.f + expf(-acc));
}

// ---- qkt[bt][h] = dot(q_row, k_row): one warp per (row, head) ----
__global__ void qk_kernel(const float* __restrict__ q, const float* __restrict__ k,
                          float* __restrict__ out) {
    int row = blockIdx.x;
    int h = threadIdx.x >> 5;
    int l = threadIdx.x & 31;
    size_t base = (size_t)row * HIDN + h * Dd + l * 4;
    float4 a = *(const float4*)(q + base);
    float4 b = *(const float4*)(k + base);
    float acc = a.x * b.x;
    acc = fmaf(a.y, b.y, acc);
    acc = fmaf(a.z, b.z, acc);
    acc = fmaf(a.w, b.w, acc);
#pragma unroll
    for (int off = 16; off > 0; off >>= 1) acc += __shfl_xor_sync(0xffffffffu, acc, off);
    if (l == 0) out[row * Hh + h] = acc;
}

// -------- depthwise causal conv (K=4) + SiLU + optional per-head RMSNorm --------
__global__ void conv_silu_norm(const float* __restrict__ pre_base, const float* __restrict__ wq,
                               const float* __restrict__ wk, const float* __restrict__ wv,
                               float* __restrict__ out_base) {
    int which = blockIdx.y;
    const float* w = (which == 0) ? wq : (which == 1 ? wk : wv);
    const float* pre = pre_base + (size_t)which * BT * HIDN;
    float* out = out_base + (size_t)which * BT * HIDN;
    float postscale = (which == 0) ? (1.f / 128.f) : (which == 1 ? 0.08838834764831845f : 1.f);
    int do_norm = (which < 2);

    int blk = blockIdx.x;
    int h = blk % Hh;
    int bt = blk / Hh;
    int t = bt % Tq;
    int d = threadIdx.x;
    int c = h * Dd + d;

    float acc = 0.f;
#pragma unroll
    for (int j = 0; j < 4; j++) {
        int tt = t - 3 + j;
        if (tt >= 0) acc += pre[(size_t)(bt - t + tt) * HIDN + c] * w[c * 4 + j];
    }
    acc = acc / (1.f + expf(-acc));
    float val = acc;
    if (do_norm) {
        float ss = acc * acc;
#pragma unroll
        for (int off = 16; off > 0; off >>= 1) ss += __shfl_xor_sync(0xffffffffu, ss, off);
        __shared__ float sh[4];
        if ((threadIdx.x & 31) == 0) sh[threadIdx.x >> 5] = ss;
        __syncthreads();
        float tot = sh[0] + sh[1] + sh[2] + sh[3];
        val = acc * rsqrtf(tot * (1.f / 128.f) + 1e-6f) * postscale;
    }
    out[(size_t)bt * HIDN + c] = val;
}

// -------- eg = exp(-exp(A_log[h]) * softplus(a + dt_bias)) --------
__global__ void g_transform(float* __restrict__ a, const float* __restrict__ dt_bias,
                            const float* __restrict__ A_log) {
    int idx = blockIdx.x * blockDim.x + threadIdx.x;
    if (idx >= BT * HIDN) return;
    int c = idx % HIDN;
    int h = c / Dd;
    float x = a[idx] + dt_bias[c];
    float sp = (x > 0.f) ? (x + log1pf(expf(-x))) : log1pf(expf(x));
    a[idx] = expf(-expf(A_log[h]) * sp);
}

// ------- gated delta-rule scan: 32 lanes/col (R12 structure), qk hoisted -------
// grid (16 bh, 32 colgroups of 4), 128 threads (4 warps = 4 cols).
// Per step: s = S·e; kv=k·s, qs=q·s partials; one 5-level x2 butterfly;
// delta = b(v-kv); o = qs + qkt*delta; S = s + k*delta.
__global__ void __launch_bounds__(128, 4)
scan_kernel(const float* __restrict__ q, const float* __restrict__ k,
            const float* __restrict__ v, const float* __restrict__ eg,
            const float* __restrict__ beta, const float* __restrict__ qkt,
            float* __restrict__ out) {
    int bh = blockIdx.x;
    int b = bh >> 3, h = bh & 7;
    int warp = threadIdx.x >> 5, lane = threadIdx.x & 31;
    int col = blockIdx.y * 4 + warp;
    int rbase = lane * 4;
    size_t rowbase = (size_t)b * Tq * HIDN + h * Dd;
    int sbase = b * Tq * Hh + h;

    float4 S = make_float4(0.f, 0.f, 0.f, 0.f);

    float4 kc, qc, ec;
    float vc, bc, qkc;
    kc = *(const float4*)(k  + rowbase + rbase);
    qc = *(const float4*)(q  + rowbase + rbase);
    ec = *(const float4*)(eg + rowbase + rbase);
    vc = v[rowbase + col];
    bc = beta[sbase];
    qkc = qkt[sbase];

    for (int t = 0; t < Tq; t++) {
        size_t row = rowbase + (size_t)t * HIDN;
        // unconditional clamped prefetch of step t+1 (R12 structure)
        int tn = (t + 1 < Tq) ? (t + 1) : t;
        size_t rown = rowbase + (size_t)tn * HIDN;
        float4 kn = *(const float4*)(k  + rown + rbase);
        float4 qn = *(const float4*)(q  + rown + rbase);
        float4 en = *(const float4*)(eg + rown + rbase);
        float vn_ = v[rown + col];
        float bn_ = beta[sbase + tn * Hh];
        float qkn = qkt[sbase + tn * Hh];

        // phase 1: decay + two partial sums (qk precomputed)
        float s0 = S.x * ec.x, s1 = S.y * ec.y, s2 = S.z * ec.z, s3 = S.w * ec.w;
        float kv = kc.x * s0; kv = fmaf(kc.y, s1, kv); kv = fmaf(kc.z, s2, kv); kv = fmaf(kc.w, s3, kv);
        float qs = qc.x * s0; qs = fmaf(qc.y, s1, qs); qs = fmaf(qc.z, s2, qs); qs = fmaf(qc.w, s3, qs);

        // one batch of 2 interleaved 32-lane butterfly reductions
#pragma unroll
        for (int off = 1; off < 32; off <<= 1) {
            kv += __shfl_xor_sync(0xffffffffu, kv, off);
            qs += __shfl_xor_sync(0xffffffffu, qs, off);
        }
        float delta = bc * (vc - kv);
        if (lane == 0) out[row + col] = fmaf(qkc, delta, qs);

        // phase 2: state update
        S.x = fmaf(kc.x, delta, s0);
        S.y = fmaf(kc.y, delta, s1);
        S.z = fmaf(kc.z, delta, s2);
        S.w = fmaf(kc.w, delta, s3);

        kc = kn; qc = qn; ec = en; vc = vn_; bc = bn_; qkc = qkn;
    }
}

// -------- output RMSNorm * o_norm_w * sigmoid(gate); writes tf32-rounded --------
__global__ void out_norm_gate(float* __restrict__ attn, const float* __restrict__ gate,
                              const float* __restrict__ onw) {
    int blk = blockIdx.x;
    int h = blk % Hh;
    int bt = blk / Hh;
    int d = threadIdx.x;
    size_t idx = (size_t)bt * HIDN + h * Dd + d;
    float val = attn[idx];
    float ss = val * val;
#pragma unroll
    for (int off = 16; off > 0; off >>= 1) ss += __shfl_xor_sync(0xffffffffu, ss, off);
    __shared__ float sh[4];
    if ((threadIdx.x & 31) == 0) sh[threadIdx.x >> 5] = ss;
    __syncthreads();
    float tot = sh[0] + sh[1] + sh[2] + sh[3];
    float gt = gate[idx];
    attn[idx] = tf32r(val * rsqrtf(tot * (1.f / 128.f) + 1e-5f) * onw[d]
              * (1.f / (1.f + expf(-gt))));
}

// ---------------------------------- launch ----------------------------------
extern "C" void kernel_launch(void* const* d_in, const int* in_sizes, int n_in,
                              void* d_out, int out_size) {
    const float* x       = (const float*)d_in[0];
    const float* Wq      = (const float*)d_in[1];
    const float* Wk      = (const float*)d_in[2];
    const float* Wv      = (const float*)d_in[3];
    const float* wq_conv = (const float*)d_in[4];
    const float* wk_conv = (const float*)d_in[5];
    const float* wv_conv = (const float*)d_in[6];
    const float* Wfa     = (const float*)d_in[7];
    const float* Wfb     = (const float*)d_in[8];
    const float* Wb      = (const float*)d_in[9];
    const float* Wga     = (const float*)d_in[10];
    const float* Wgb     = (const float*)d_in[11];
    const float* A_log   = (const float*)d_in[12];
    const float* dt_bias = (const float*)d_in[13];
    const float* onw     = (const float*)d_in[14];
    const float* Wo      = (const float*)d_in[15];
    float* out = (float*)d_out;

    float *pre, *qkvn, *nar, *lr, *betab, *qkt, *attn, *xtf, *wtf;
    cudaGetSymbolAddress((void**)&pre, g_pre);
    cudaGetSymbolAddress((void**)&qkvn, g_qkvn);
    cudaGetSymbolAddress((void**)&nar, g_nar);
    cudaGetSymbolAddress((void**)&lr, g_lr);
    cudaGetSymbolAddress((void**)&betab, g_betab);
    cudaGetSymbolAddress((void**)&qkt, g_qkt);
    cudaGetSymbolAddress((void**)&attn, g_attn);
    cudaGetSymbolAddress((void**)&xtf, g_xtf);
    cudaGetSymbolAddress((void**)&wtf, g_wtf);

    const size_t S1 = (size_t)BT * HIDN;
    const size_t SD = (size_t)BT * Dd;
    const int SMEM_GEMM = 4 * CHUNK_BYTES + 1024;   // 66560
    cudaFuncSetAttribute(gemm_tc, cudaFuncAttributeMaxDynamicSharedMemorySize, SMEM_GEMM);

    // side streams + events, created ONCE on the first (uncaptured) call
    static cudaStream_t s1 = nullptr, s2 = nullptr;
    static cudaEvent_t evFork = nullptr, ev1 = nullptr, ev2 = nullptr;
    if (!s1) {
        cudaStreamCreateWithFlags(&s1, cudaStreamNonBlocking);
        cudaStreamCreateWithFlags(&s2, cudaStreamNonBlocking);
        cudaEventCreateWithFlags(&evFork, cudaEventDisableTiming);
        cudaEventCreateWithFlags(&ev1, cudaEventDisableTiming);
        cudaEventCreateWithFlags(&ev2, cudaEventDisableTiming);
    }

    // fork: beta depends only on raw x
    cudaEventRecord(evFork, 0);
    cudaStreamWaitEvent(s2, evFork, 0);
    beta_kernel<<<BT, 256, 0, s2>>>(x, Wb, betab);
    cudaEventRecord(ev2, s2);

    // tf32 pre-conversion on main stream
    cvt_tf32_all<<<dim3(2048, 9), 256>>>(x, Wq, Wk, Wv, Wo, Wfa, Wga, Wfb, Wgb);
    cudaEventRecord(evFork, 0);
    cudaStreamWaitEvent(s1, evFork, 0);

    // side branch on s1: nar -> lr -> g_transform
    gemm_tc<<<dim3(1, 16, 2), 256, SMEM_GEMM, s1>>>(xtf, 0, wtf + OWFA, wtf + OWGA, wtf + OWGA,
                                                    nar, SD, Dd, HIDN, 1);
    gemm_tc<<<dim3(8, 16, 2), 256, SMEM_GEMM, s1>>>(nar, SD, wtf + OWFB, wtf + OWGB, wtf + OWGB,
                                                    lr, S1, HIDN, Dd, 0);
    g_transform<<<(BT * HIDN + 255) / 256, 256, 0, s1>>>(lr, dt_bias, A_log);
    cudaEventRecord(ev1, s1);

    // main branch: QKV projections -> conv/silu/norm -> qk precompute
    gemm_tc<<<dim3(8, 16, 3), 256, SMEM_GEMM>>>(xtf, 0, wtf + OWQ, wtf + OWK, wtf + OWV,
                                                pre, S1, HIDN, HIDN, 0);
    conv_silu_norm<<<dim3(BT * Hh, 3), 128>>>(pre, wq_conv, wk_conv, wv_conv, qkvn);
    qk_kernel<<<BT, 256>>>(qkvn, qkvn + S1, qkt);

    // join: scan needs qkvn+qkt (main), lr (s1), betab (s2)
    cudaStreamWaitEvent(0, ev1, 0);
    cudaStreamWaitEvent(0, ev2, 0);

    // recurrence (R12 structure + hoisted qk: 2-chain butterfly)
    scan_kernel<<<dim3(16, 32), 128>>>(qkvn, qkvn + S1, qkvn + 2 * S1, lr, betab, qkt, attn);

    // output norm/gate (writes tf32-rounded attn) + final projection
    out_norm_gate<<<BT * Hh, 128>>>(attn, lr + S1, onw);
    gemm_tc<<<dim3(8, 16, 1), 256, SMEM_GEMM>>>(attn, 0, wtf + OWO, wtf + OWO, wtf + OWO,
                                                out, 0, HIDN, HIDN, 0);
}